// round 8
// baseline (speedup 1.0000x reference)
#include <cuda_runtime.h>
#include <cuda_fp16.h>

#define NN 65536
#define NE 1048576
#define DIN 1024
#define DH 64
#define NC 32

// ---------------- scratch (static device globals; no allocs) ----------------
__device__ int     g_is64;
__device__ int     g_tile;
__device__ int     g_deg[NN];
__device__ int     g_scan[NN];
__device__ int     g_bsum[64];
__device__ int     g_rowptr[NN + 1];
__device__ int     g_cursor[NN];
__device__ int     g_col[NE];
__device__ float   g_dinv[NN];
__device__ __half2 g_y1h[(size_t)NN * 32];   // y1 = x@W1 (unscaled), fp16 pairs
__device__ __half  g_y2h[(size_t)NN * NC];   // y2 = dinv*(h@W2), fp16
__device__ __half  g_w1h[DH * DIN];          // W1^T fp16: [n][k]

// ---------------- dtype detect + zero deg ----------------
__global__ void k_detect(const int* __restrict__ w) {
    __shared__ int s[1024];
    int t = threadIdx.x;
    int acc = 0;
    for (int i = t; i < 16384; i += 1024) acc |= w[2 * i + 1];
    s[t] = acc;
    for (int i = t; i < NN; i += 1024) g_deg[i] = 0;
    __syncthreads();
    for (int off = 512; off; off >>= 1) {
        if (t < off) s[t] |= s[t + off];
        __syncthreads();
    }
    if (t == 0) g_is64 = (s[0] == 0) ? 1 : 0;
}

__global__ void k_prep(const int* __restrict__ w) {
    int i = blockIdx.x * blockDim.x + threadIdx.x;
    if (i >= NE) return;
    int d = g_is64 ? w[2 * (NE + i)] : w[NE + i];
    atomicAdd(&g_deg[d & (NN - 1)], 1);
}

__global__ void k_scan1() {
    __shared__ int s[1024];
    int t = threadIdx.x;
    int gid = blockIdx.x * 1024 + t;
    s[t] = g_deg[gid];
    __syncthreads();
    for (int off = 1; off < 1024; off <<= 1) {
        int v = (t >= off) ? s[t - off] : 0;
        __syncthreads();
        s[t] += v;
        __syncthreads();
    }
    g_scan[gid] = s[t];
    if (t == 1023) g_bsum[blockIdx.x] = s[t];
}

// fused: per-block redundant 64-entry scan of g_bsum, then rowptr/cursor/dinv
__global__ void k_scan3() {
    __shared__ int sb[64];
    int t = threadIdx.x;
    if (t < 64) sb[t] = g_bsum[t];
    __syncthreads();
#pragma unroll
    for (int off = 1; off < 64; off <<= 1) {
        int v = (t < 64 && t >= off) ? sb[t - off] : 0;
        __syncthreads();
        if (t < 64) sb[t] += v;
        __syncthreads();
    }
    int i = blockIdx.x * blockDim.x + t;
    if (i >= NN) return;
    int blk = i >> 10;
    int boff = (blk ? sb[blk - 1] : 0);
    int excl = g_scan[i] - g_deg[i] + boff;
    g_rowptr[i] = excl;
    g_cursor[i] = excl;
    g_dinv[i] = rsqrtf((float)g_deg[i] + 1.0f);
    if (i == 0) g_rowptr[NN] = NE;
}

__global__ void k_fill(const int* __restrict__ w) {
    int i = blockIdx.x * blockDim.x + threadIdx.x;
    if (i >= NE) return;
    int s, d;
    if (g_is64) { s = w[2 * i]; d = w[2 * (NE + i)]; }
    else        { s = w[i];     d = w[NE + i]; }
    int p = atomicAdd(&g_cursor[d & (NN - 1)], 1);
    g_col[p] = s & (NN - 1);
}

// ---------------- W1 fp16 transpose + tile-counter reset ----------------
__global__ void k_wconv(const float* __restrict__ W1) {
    int i = blockIdx.x * blockDim.x + threadIdx.x;  // i = k*64+n
    if (i == 0) g_tile = 0;
    if (i >= DIN * DH) return;
    int k = i >> 6, n = i & 63;
    g_w1h[n * DIN + k] = __float2half_rn(W1[i]);
}

// ---------------- GEMM1 (HMMA fp16, ldmatrix, double-buffered, persistent) ----------------
#define SAS 40

__device__ __forceinline__ unsigned smem_u32(const void* p) {
    unsigned a;
    asm("{ .reg .u64 t; cvta.to.shared.u64 t, %1; cvt.u32.u64 %0, t; }" : "=r"(a) : "l"(p));
    return a;
}
__device__ __forceinline__ void ldsm4(unsigned* r, unsigned addr) {
    asm volatile("ldmatrix.sync.aligned.m8n8.x4.shared.b16 {%0,%1,%2,%3}, [%4];"
                 : "=r"(r[0]), "=r"(r[1]), "=r"(r[2]), "=r"(r[3]) : "r"(addr));
}
__device__ __forceinline__ void mma16816(float* d, const unsigned* a, const unsigned* b) {
    asm("mma.sync.aligned.m16n8k16.row.col.f32.f16.f16.f32 "
        "{%0,%1,%2,%3}, {%4,%5,%6,%7}, {%8,%9}, {%0,%1,%2,%3};"
        : "+f"(d[0]), "+f"(d[1]), "+f"(d[2]), "+f"(d[3])
        : "r"(a[0]), "r"(a[1]), "r"(a[2]), "r"(a[3]), "r"(b[0]), "r"(b[1]));
}

#define NTILES (NN / 128)

__global__ __launch_bounds__(256, 3) void k_gemm1t(const float* __restrict__ A) {
    __shared__ __half Ah[2][128][SAS], Bh[2][64][SAS];
    __shared__ int s_tile;

    int tid = threadIdx.x;
    int wid = tid >> 5, lane = tid & 31;
    int wm = wid >> 1, wn = wid & 1;
    int g = lane >> 2, t = lane & 3;
    const unsigned* w1h32 = (const unsigned*)g_w1h;

    int a_lrow = (lane & 15);
    int a_lcol = (lane >> 4) * 8;
    unsigned aAddr[2][2], bAddr[2];
#pragma unroll
    for (int bu = 0; bu < 2; bu++) {
#pragma unroll
        for (int mt = 0; mt < 2; mt++) {
            int r0 = wm * 32 + mt * 16;
            aAddr[bu][mt] = smem_u32(&Ah[bu][r0 + a_lrow][a_lcol]);
        }
        bAddr[bu] = smem_u32(&Bh[bu][wn * 32 + lane][0]);
    }

    int srow = tid >> 3, skq = (tid & 7) * 4;   // + i*32 rows
    int sbr  = tid >> 4, sbc = tid & 15;        // + i*16 rows

    for (;;) {
        if (tid == 0) s_tile = atomicAdd(&g_tile, 1);
        __syncthreads();
        int tile = s_tile;
        if (tile >= NTILES) break;
        int blockRow = tile * 128;

        float acc[2][4][4];
#pragma unroll
        for (int mt = 0; mt < 2; mt++)
#pragma unroll
            for (int nt = 0; nt < 4; nt++)
#pragma unroll
                for (int q = 0; q < 4; q++) acc[mt][nt][q] = 0.0f;

        float4 av[4];
        unsigned bhv[4];
#pragma unroll
        for (int i = 0; i < 4; i++) {
            av[i]  = *(const float4*)(A + (size_t)(blockRow + srow + i * 32) * DIN + skq);
            bhv[i] = w1h32[(sbr + i * 16) * (DIN / 2) + sbc];
        }
#pragma unroll
        for (int i = 0; i < 4; i++) {
            __half2 h01 = __float22half2_rn(make_float2(av[i].x, av[i].y));
            __half2 h23 = __float22half2_rn(make_float2(av[i].z, av[i].w));
            *(uint2*)&Ah[0][srow + i * 32][skq] = make_uint2(*(unsigned*)&h01, *(unsigned*)&h23);
            *(unsigned*)&Bh[0][sbr + i * 16][sbc * 2] = bhv[i];
        }
        __syncthreads();

        for (int c = 0; c < 32; c++) {
            int bu = c & 1;
            if (c + 1 < 32) {
                int kt = (c + 1) * 32;
#pragma unroll
                for (int i = 0; i < 4; i++) {
                    av[i]  = *(const float4*)(A + (size_t)(blockRow + srow + i * 32) * DIN + kt + skq);
                    bhv[i] = w1h32[(sbr + i * 16) * (DIN / 2) + kt / 2 + sbc];
                }
            }

#pragma unroll
            for (int kk = 0; kk < 32; kk += 16) {
                unsigned ah[2][4], bb[2][4];
#pragma unroll
                for (int mt = 0; mt < 2; mt++)
                    ldsm4(ah[mt], aAddr[bu][mt] + kk * 2);
                ldsm4(bb[0], bAddr[bu] + kk * 2);
                ldsm4(bb[1], bAddr[bu] + (kk + 8) * 2);
#pragma unroll
                for (int mt = 0; mt < 2; mt++)
#pragma unroll
                    for (int nt = 0; nt < 4; nt++) {
                        unsigned bfr[2] = { bb[0][nt], bb[1][nt] };
                        mma16816(acc[mt][nt], ah[mt], bfr);
                    }
            }

            if (c + 1 < 32) {
#pragma unroll
                for (int i = 0; i < 4; i++) {
                    __half2 h01 = __float22half2_rn(make_float2(av[i].x, av[i].y));
                    __half2 h23 = __float22half2_rn(make_float2(av[i].z, av[i].w));
                    *(uint2*)&Ah[bu ^ 1][srow + i * 32][skq] =
                        make_uint2(*(unsigned*)&h01, *(unsigned*)&h23);
                    *(unsigned*)&Bh[bu ^ 1][sbr + i * 16][sbc * 2] = bhv[i];
                }
            }
            __syncthreads();
        }

        // epilogue: store raw x@W1 as half2 (dinv applied in aggregation)
#pragma unroll
        for (int mt = 0; mt < 2; mt++) {
            int r0 = blockRow + wm * 32 + mt * 16 + g;
            int r1 = r0 + 8;
#pragma unroll
            for (int nt = 0; nt < 4; nt++) {
                int ci = wn * 16 + nt * 4 + t;
                g_y1h[(size_t)r0 * 32 + ci] = __floats2half2_rn(acc[mt][nt][0], acc[mt][nt][1]);
                g_y1h[(size_t)r1 * 32 + ci] = __floats2half2_rn(acc[mt][nt][2], acc[mt][nt][3]);
            }
        }
        __syncthreads();
    }
}

// ---------------- layer-1 aggregation + relu + GEMM2 fused (warp per node) ----------------
__global__ __launch_bounds__(256) void k_agg1g2(const float* __restrict__ b1,
                                                const float* __restrict__ W2) {
    __shared__ float Ws[DH * NC];
    for (int i = threadIdx.x; i < DH * NC; i += 256) Ws[i] = W2[i];
    __syncthreads();

    int warp = (blockIdx.x * blockDim.x + threadIdx.x) >> 5;
    int lane = threadIdx.x & 31;
    if (warp >= NN) return;

    const __half2* yp = g_y1h;
    float dv = g_dinv[warp];
    float2 self = __half22float2(yp[(size_t)warp * 32 + lane]);
    float2 a = make_float2(dv * self.x, dv * self.y);
    int e = g_rowptr[warp], e1 = g_rowptr[warp + 1];
    for (; e + 4 <= e1; e += 4) {
        int s0 = g_col[e], s1 = g_col[e + 1], s2 = g_col[e + 2], s3 = g_col[e + 3];
        float d0 = __ldg(&g_dinv[s0]), d1 = __ldg(&g_dinv[s1]);
        float d2 = __ldg(&g_dinv[s2]), d3 = __ldg(&g_dinv[s3]);
        float2 v0 = __half22float2(yp[(size_t)s0 * 32 + lane]);
        float2 v1 = __half22float2(yp[(size_t)s1 * 32 + lane]);
        float2 v2 = __half22float2(yp[(size_t)s2 * 32 + lane]);
        float2 v3 = __half22float2(yp[(size_t)s3 * 32 + lane]);
        a.x += (d0 * v0.x + d1 * v1.x) + (d2 * v2.x + d3 * v3.x);
        a.y += (d0 * v0.y + d1 * v1.y) + (d2 * v2.y + d3 * v3.y);
    }
    for (; e < e1; e++) {
        int s = g_col[e];
        float ds = __ldg(&g_dinv[s]);
        float2 v = __half22float2(yp[(size_t)s * 32 + lane]);
        a.x += ds * v.x; a.y += ds * v.y;
    }

    float2 bb = ((const float2*)b1)[lane];
    float hx = fmaxf(fmaf(dv, a.x, bb.x), 0.0f);
    float hy = fmaxf(fmaf(dv, a.y, bb.y), 0.0f);

    float acc2 = 0.0f;
#pragma unroll
    for (int k2 = 0; k2 < 32; k2++) {
        float sx = __shfl_sync(0xffffffffu, hx, k2);
        float sy = __shfl_sync(0xffffffffu, hy, k2);
        acc2 = fmaf(sx, Ws[(2 * k2) * NC + lane], acc2);
        acc2 = fmaf(sy, Ws[(2 * k2 + 1) * NC + lane], acc2);
    }
    g_y2h[(size_t)warp * NC + lane] = __float2half_rn(acc2 * dv);
}

// ---------------- layer-2 aggregation + bias + log_softmax ----------------
__global__ __launch_bounds__(256) void k_agg2(const float* __restrict__ b2,
                                              float* __restrict__ out) {
    int warp = (blockIdx.x * blockDim.x + threadIdx.x) >> 5;
    int lane = threadIdx.x & 31;
    if (warp >= NN) return;
    float a = __half2float(g_y2h[(size_t)warp * NC + lane]);
    int e = g_rowptr[warp], e1 = g_rowptr[warp + 1];
    for (; e + 4 <= e1; e += 4) {
        int s0 = g_col[e], s1 = g_col[e + 1], s2 = g_col[e + 2], s3 = g_col[e + 3];
        float v0 = __half2float(g_y2h[(size_t)s0 * NC + lane]);
        float v1 = __half2float(g_y2h[(size_t)s1 * NC + lane]);
        float v2 = __half2float(g_y2h[(size_t)s2 * NC + lane]);
        float v3 = __half2float(g_y2h[(size_t)s3 * NC + lane]);
        a += (v0 + v1) + (v2 + v3);
    }
    for (; e < e1; e++) a += __half2float(g_y2h[(size_t)g_col[e] * NC + lane]);

    float v = fmaf(g_dinv[warp], a, b2[lane]);
    float mx = v;
#pragma unroll
    for (int o = 16; o; o >>= 1) mx = fmaxf(mx, __shfl_xor_sync(0xffffffffu, mx, o));
    float ex = __expf(v - mx);
    float sm = ex;
#pragma unroll
    for (int o = 16; o; o >>= 1) sm += __shfl_xor_sync(0xffffffffu, sm, o);
    out[(size_t)warp * NC + lane] = v - mx - logf(sm);
}

// ---------------- launch (gemm1t at index 3 so ncu profiles it) ----------------
extern "C" void kernel_launch(void* const* d_in, const int* in_sizes, int n_in,
                              void* d_out, int out_size) {
    const float* x  = (const float*)d_in[0];
    const int*   ei = (const int*)d_in[1];
    const float* W1 = (const float*)d_in[2];
    const float* b1 = (const float*)d_in[3];
    const float* W2 = (const float*)d_in[4];
    const float* b2 = (const float*)d_in[5];
    float* out = (float*)d_out;

    k_detect<<<1, 1024>>>(ei);
    k_prep  <<<NE / 256, 256>>>(ei);
    k_wconv <<<(DIN * DH + 255) / 256, 256>>>(W1);
    k_gemm1t<<<444, 256>>>(x);
    k_scan1 <<<64, 1024>>>();
    k_scan3 <<<NN / 256, 256>>>();
    k_fill  <<<NE / 256, 256>>>(ei);
    k_agg1g2<<<NN / 8, 256>>>(b1, W2);
    k_agg2  <<<NN / 8, 256>>>(b2, out);
}

// round 9
// speedup vs baseline: 1.0492x; 1.0492x over previous
#include <cuda_runtime.h>
#include <cuda_fp16.h>

#define NN 65536
#define NE 1048576
#define DIN 1024
#define DH 64
#define NC 32

// ---------------- scratch (static device globals; no allocs) ----------------
__device__ int     g_is64;
__device__ int     g_tile;
__device__ int     g_deg[NN];
__device__ int     g_scan[NN];
__device__ int     g_bsum[64];
__device__ int     g_rowptr[NN + 1];
__device__ int     g_cursor[NN];
__device__ int     g_col[NE];
__device__ float   g_dinv[NN];
__device__ __half2 g_y1h[(size_t)NN * 32];   // y1 = dinv*(x@W1), fp16 pairs
__device__ __half  g_y2h[(size_t)NN * NC];   // y2 = dinv*(h@W2), fp16
__device__ __half  g_w1h[DH * DIN];          // W1^T fp16: [n][k]

// ---------------- dtype detect + zero deg ----------------
__global__ void k_detect(const int* __restrict__ w) {
    __shared__ int s[1024];
    int t = threadIdx.x;
    int acc = 0;
    for (int i = t; i < 16384; i += 1024) acc |= w[2 * i + 1];
    s[t] = acc;
    for (int i = t; i < NN; i += 1024) g_deg[i] = 0;
    __syncthreads();
    for (int off = 512; off; off >>= 1) {
        if (t < off) s[t] |= s[t + off];
        __syncthreads();
    }
    if (t == 0) g_is64 = (s[0] == 0) ? 1 : 0;
}

__global__ void k_prep(const int* __restrict__ w) {
    int i = blockIdx.x * blockDim.x + threadIdx.x;
    if (i >= NE) return;
    int d = g_is64 ? w[2 * (NE + i)] : w[NE + i];
    atomicAdd(&g_deg[d & (NN - 1)], 1);
}

// ---------------- W1 fp16 transpose + dinv + tile-counter reset ----------------
__global__ void k_wconv(const float* __restrict__ W1) {
    int i = blockIdx.x * blockDim.x + threadIdx.x;  // i in [0, 65536)
    if (i == 0) g_tile = 0;
    if (i >= DIN * DH) return;
    int k = i >> 6, n = i & 63;
    g_w1h[n * DIN + k] = __float2half_rn(W1[i]);
    g_dinv[i] = rsqrtf((float)g_deg[i] + 1.0f);   // deg counted by k_prep
}

// ---------------- GEMM1 (HMMA fp16, ldmatrix, double-buffered, persistent) ----------------
#define SAS 40

__device__ __forceinline__ unsigned smem_u32(const void* p) {
    unsigned a;
    asm("{ .reg .u64 t; cvta.to.shared.u64 t, %1; cvt.u32.u64 %0, t; }" : "=r"(a) : "l"(p));
    return a;
}
__device__ __forceinline__ void ldsm4(unsigned* r, unsigned addr) {
    asm volatile("ldmatrix.sync.aligned.m8n8.x4.shared.b16 {%0,%1,%2,%3}, [%4];"
                 : "=r"(r[0]), "=r"(r[1]), "=r"(r[2]), "=r"(r[3]) : "r"(addr));
}
__device__ __forceinline__ void mma16816(float* d, const unsigned* a, const unsigned* b) {
    asm("mma.sync.aligned.m16n8k16.row.col.f32.f16.f16.f32 "
        "{%0,%1,%2,%3}, {%4,%5,%6,%7}, {%8,%9}, {%0,%1,%2,%3};"
        : "+f"(d[0]), "+f"(d[1]), "+f"(d[2]), "+f"(d[3])
        : "r"(a[0]), "r"(a[1]), "r"(a[2]), "r"(a[3]), "r"(b[0]), "r"(b[1]));
}

#define NTILES (NN / 128)

__global__ __launch_bounds__(256, 3) void k_gemm1t(const float* __restrict__ A) {
    __shared__ __half Ah[2][128][SAS], Bh[2][64][SAS];
    __shared__ int s_tile;

    int tid = threadIdx.x;
    int wid = tid >> 5, lane = tid & 31;
    int wm = wid >> 1, wn = wid & 1;
    int g = lane >> 2, t = lane & 3;
    const unsigned* w1h32 = (const unsigned*)g_w1h;

    int a_lrow = (lane & 15);
    int a_lcol = (lane >> 4) * 8;
    unsigned aAddr[2][2], bAddr[2];
#pragma unroll
    for (int bu = 0; bu < 2; bu++) {
#pragma unroll
        for (int mt = 0; mt < 2; mt++) {
            int r0 = wm * 32 + mt * 16;
            aAddr[bu][mt] = smem_u32(&Ah[bu][r0 + a_lrow][a_lcol]);
        }
        bAddr[bu] = smem_u32(&Bh[bu][wn * 32 + lane][0]);
    }

    int srow = tid >> 3, skq = (tid & 7) * 4;   // + i*32 rows
    int sbr  = tid >> 4, sbc = tid & 15;        // + i*16 rows

    for (;;) {
        if (tid == 0) s_tile = atomicAdd(&g_tile, 1);
        __syncthreads();
        int tile = s_tile;
        if (tile >= NTILES) break;
        int blockRow = tile * 128;

        float acc[2][4][4];
#pragma unroll
        for (int mt = 0; mt < 2; mt++)
#pragma unroll
            for (int nt = 0; nt < 4; nt++)
#pragma unroll
                for (int q = 0; q < 4; q++) acc[mt][nt][q] = 0.0f;

        float4 av[4];
        unsigned bhv[4];
#pragma unroll
        for (int i = 0; i < 4; i++) {
            av[i]  = *(const float4*)(A + (size_t)(blockRow + srow + i * 32) * DIN + skq);
            bhv[i] = w1h32[(sbr + i * 16) * (DIN / 2) + sbc];
        }
#pragma unroll
        for (int i = 0; i < 4; i++) {
            __half2 h01 = __float22half2_rn(make_float2(av[i].x, av[i].y));
            __half2 h23 = __float22half2_rn(make_float2(av[i].z, av[i].w));
            *(uint2*)&Ah[0][srow + i * 32][skq] = make_uint2(*(unsigned*)&h01, *(unsigned*)&h23);
            *(unsigned*)&Bh[0][sbr + i * 16][sbc * 2] = bhv[i];
        }
        __syncthreads();

        for (int c = 0; c < 32; c++) {
            int bu = c & 1;
            if (c + 1 < 32) {
                int kt = (c + 1) * 32;
#pragma unroll
                for (int i = 0; i < 4; i++) {
                    av[i]  = *(const float4*)(A + (size_t)(blockRow + srow + i * 32) * DIN + kt + skq);
                    bhv[i] = w1h32[(sbr + i * 16) * (DIN / 2) + kt / 2 + sbc];
                }
            }

#pragma unroll
            for (int kk = 0; kk < 32; kk += 16) {
                unsigned ah[2][4], bb[2][4];
#pragma unroll
                for (int mt = 0; mt < 2; mt++)
                    ldsm4(ah[mt], aAddr[bu][mt] + kk * 2);
                ldsm4(bb[0], bAddr[bu] + kk * 2);
                ldsm4(bb[1], bAddr[bu] + (kk + 8) * 2);
#pragma unroll
                for (int mt = 0; mt < 2; mt++)
#pragma unroll
                    for (int nt = 0; nt < 4; nt++) {
                        unsigned bfr[2] = { bb[0][nt], bb[1][nt] };
                        mma16816(acc[mt][nt], ah[mt], bfr);
                    }
            }

            if (c + 1 < 32) {
#pragma unroll
                for (int i = 0; i < 4; i++) {
                    __half2 h01 = __float22half2_rn(make_float2(av[i].x, av[i].y));
                    __half2 h23 = __float22half2_rn(make_float2(av[i].z, av[i].w));
                    *(uint2*)&Ah[bu ^ 1][srow + i * 32][skq] =
                        make_uint2(*(unsigned*)&h01, *(unsigned*)&h23);
                    *(unsigned*)&Bh[bu ^ 1][sbr + i * 16][sbc * 2] = bhv[i];
                }
            }
            __syncthreads();
        }

        // epilogue: scale by dinv, store as half2
#pragma unroll
        for (int mt = 0; mt < 2; mt++) {
            int r0 = blockRow + wm * 32 + mt * 16 + g;
            int r1 = r0 + 8;
            float d0 = g_dinv[r0], d1 = g_dinv[r1];
#pragma unroll
            for (int nt = 0; nt < 4; nt++) {
                int ci = wn * 16 + nt * 4 + t;
                g_y1h[(size_t)r0 * 32 + ci] =
                    __floats2half2_rn(acc[mt][nt][0] * d0, acc[mt][nt][1] * d0);
                g_y1h[(size_t)r1 * 32 + ci] =
                    __floats2half2_rn(acc[mt][nt][2] * d1, acc[mt][nt][3] * d1);
            }
        }
        __syncthreads();
    }
}

// ---------------- scans / CSR ----------------
__global__ void k_scan1() {
    __shared__ int s[1024];
    int t = threadIdx.x;
    int gid = blockIdx.x * 1024 + t;
    s[t] = g_deg[gid];
    __syncthreads();
    for (int off = 1; off < 1024; off <<= 1) {
        int v = (t >= off) ? s[t - off] : 0;
        __syncthreads();
        s[t] += v;
        __syncthreads();
    }
    g_scan[gid] = s[t];
    if (t == 1023) g_bsum[blockIdx.x] = s[t];
}

__global__ void k_scan3() {
    __shared__ int sb[64];
    int t = threadIdx.x;
    if (t < 64) sb[t] = g_bsum[t];
    __syncthreads();
#pragma unroll
    for (int off = 1; off < 64; off <<= 1) {
        int v = (t < 64 && t >= off) ? sb[t - off] : 0;
        __syncthreads();
        if (t < 64) sb[t] += v;
        __syncthreads();
    }
    int i = blockIdx.x * blockDim.x + t;
    if (i >= NN) return;
    int blk = i >> 10;
    int boff = (blk ? sb[blk - 1] : 0);
    int excl = g_scan[i] - g_deg[i] + boff;
    g_rowptr[i] = excl;
    g_cursor[i] = excl;
    if (i == 0) g_rowptr[NN] = NE;
}

__global__ void k_fill(const int* __restrict__ w) {
    int i = blockIdx.x * blockDim.x + threadIdx.x;
    if (i >= NE) return;
    int s, d;
    if (g_is64) { s = w[2 * i]; d = w[2 * (NE + i)]; }
    else        { s = w[i];     d = w[NE + i]; }
    int p = atomicAdd(&g_cursor[d & (NN - 1)], 1);
    g_col[p] = s & (NN - 1);
}

// ---------------- layer-1 aggregation + relu + GEMM2 fused (warp per node) ----------------
__global__ __launch_bounds__(256) void k_agg1g2(const float* __restrict__ b1,
                                                const float* __restrict__ W2) {
    __shared__ float Ws[DH * NC];
    for (int i = threadIdx.x; i < DH * NC; i += 256) Ws[i] = W2[i];
    __syncthreads();

    int warp = (blockIdx.x * blockDim.x + threadIdx.x) >> 5;
    int lane = threadIdx.x & 31;
    if (warp >= NN) return;

    const __half2* yp = g_y1h;
    float2 a = __half22float2(yp[(size_t)warp * 32 + lane]);
    int e = g_rowptr[warp], e1 = g_rowptr[warp + 1];
    for (; e + 8 <= e1; e += 8) {
        float2 v0 = __half22float2(yp[(size_t)g_col[e]     * 32 + lane]);
        float2 v1 = __half22float2(yp[(size_t)g_col[e + 1] * 32 + lane]);
        float2 v2 = __half22float2(yp[(size_t)g_col[e + 2] * 32 + lane]);
        float2 v3 = __half22float2(yp[(size_t)g_col[e + 3] * 32 + lane]);
        float2 v4 = __half22float2(yp[(size_t)g_col[e + 4] * 32 + lane]);
        float2 v5 = __half22float2(yp[(size_t)g_col[e + 5] * 32 + lane]);
        float2 v6 = __half22float2(yp[(size_t)g_col[e + 6] * 32 + lane]);
        float2 v7 = __half22float2(yp[(size_t)g_col[e + 7] * 32 + lane]);
        a.x += ((v0.x + v1.x) + (v2.x + v3.x)) + ((v4.x + v5.x) + (v6.x + v7.x));
        a.y += ((v0.y + v1.y) + (v2.y + v3.y)) + ((v4.y + v5.y) + (v6.y + v7.y));
    }
    for (; e < e1; e++) {
        float2 v = __half22float2(yp[(size_t)g_col[e] * 32 + lane]);
        a.x += v.x; a.y += v.y;
    }

    float dv = g_dinv[warp];
    float2 bb = ((const float2*)b1)[lane];
    float hx = fmaxf(fmaf(dv, a.x, bb.x), 0.0f);
    float hy = fmaxf(fmaf(dv, a.y, bb.y), 0.0f);

    float acc2 = 0.0f;
#pragma unroll
    for (int k2 = 0; k2 < 32; k2++) {
        float sx = __shfl_sync(0xffffffffu, hx, k2);
        float sy = __shfl_sync(0xffffffffu, hy, k2);
        acc2 = fmaf(sx, Ws[(2 * k2) * NC + lane], acc2);
        acc2 = fmaf(sy, Ws[(2 * k2 + 1) * NC + lane], acc2);
    }
    g_y2h[(size_t)warp * NC + lane] = __float2half_rn(acc2 * dv);
}

// ---------------- layer-2 aggregation + log_softmax (half-warp per node) ----------------
__global__ __launch_bounds__(256) void k_agg2(const float* __restrict__ b2,
                                              float* __restrict__ out) {
    int node = (blockIdx.x * blockDim.x + threadIdx.x) >> 4;
    int l16 = threadIdx.x & 15;
    if (node >= NN) return;
    const __half2* yp = (const __half2*)g_y2h;

    float2 a = __half22float2(yp[(size_t)node * 16 + l16]);
    int e = g_rowptr[node], e1 = g_rowptr[node + 1];
    for (; e + 4 <= e1; e += 4) {
        float2 v0 = __half22float2(yp[(size_t)g_col[e]     * 16 + l16]);
        float2 v1 = __half22float2(yp[(size_t)g_col[e + 1] * 16 + l16]);
        float2 v2 = __half22float2(yp[(size_t)g_col[e + 2] * 16 + l16]);
        float2 v3 = __half22float2(yp[(size_t)g_col[e + 3] * 16 + l16]);
        a.x += (v0.x + v1.x) + (v2.x + v3.x);
        a.y += (v0.y + v1.y) + (v2.y + v3.y);
    }
    for (; e < e1; e++) {
        float2 v = __half22float2(yp[(size_t)g_col[e] * 16 + l16]);
        a.x += v.x; a.y += v.y;
    }

    float dv = g_dinv[node];
    float2 bb = ((const float2*)b2)[l16];
    float vx = fmaf(dv, a.x, bb.x);
    float vy = fmaf(dv, a.y, bb.y);

    // log_softmax over 32 classes spread 2-per-lane across 16 lanes
    float mx = fmaxf(vx, vy);
#pragma unroll
    for (int o = 8; o; o >>= 1) mx = fmaxf(mx, __shfl_xor_sync(0xffffffffu, mx, o));
    float sm = __expf(vx - mx) + __expf(vy - mx);
#pragma unroll
    for (int o = 8; o; o >>= 1) sm += __shfl_xor_sync(0xffffffffu, sm, o);
    float lse = mx + logf(sm);
    ((float2*)out)[(size_t)node * 16 + l16] = make_float2(vx - lse, vy - lse);
}

// ---------------- launch (gemm1t at index 3 so ncu profiles it) ----------------
extern "C" void kernel_launch(void* const* d_in, const int* in_sizes, int n_in,
                              void* d_out, int out_size) {
    const float* x  = (const float*)d_in[0];
    const int*   ei = (const int*)d_in[1];
    const float* W1 = (const float*)d_in[2];
    const float* b1 = (const float*)d_in[3];
    const float* W2 = (const float*)d_in[4];
    const float* b2 = (const float*)d_in[5];
    float* out = (float*)d_out;

    k_detect<<<1, 1024>>>(ei);
    k_prep  <<<NE / 256, 256>>>(ei);
    k_wconv <<<NN / 256, 256>>>(W1);
    k_gemm1t<<<444, 256>>>(x);
    k_scan1 <<<64, 1024>>>();
    k_scan3 <<<NN / 256, 256>>>();
    k_fill  <<<NE / 256, 256>>>(ei);
    k_agg1g2<<<NN / 8, 256>>>(b1, W2);
    k_agg2  <<<NN / 16, 256>>>(b2, out);
}